// round 1
// baseline (speedup 1.0000x reference)
#include <cuda_runtime.h>
#include <math.h>

// Problem constants
#define T_LEN 2048
#define E_DIM 1024
#define D_DIM 1032   // E + H
#define NQ 8

// Intermediates (static device scratch; padded for scan prefetch overrun)
__device__ float g_xproj[(T_LEN + 8) * 32];  // [t][g*8+w], bias folded in
__device__ float g_outs[T_LEN * 8];          // h_t

// ---------------------------------------------------------------------------
// Phase 1: xproj[t][g][w] = emb[sentence[t]] . Wg[w, 0:1024] + bg[w]
// 128 blocks x 256 threads, 16 timesteps per block.
// ---------------------------------------------------------------------------
__global__ __launch_bounds__(256)
void xproj_kernel(const int* __restrict__ sentence,
                  const float* __restrict__ emb,
                  const float* __restrict__ Wf, const float* __restrict__ bf,
                  const float* __restrict__ Wi, const float* __restrict__ bi,
                  const float* __restrict__ Wu, const float* __restrict__ bu,
                  const float* __restrict__ Wo, const float* __restrict__ bo)
{
    __shared__ float xs[E_DIM];
    const float* Ws[4] = {Wf, Wi, Wu, Wo};
    const float* bs[4] = {bf, bi, bu, bo};

    const int tid  = threadIdx.x;
    const int warp = tid >> 5;
    const int lane = tid & 31;
    const int g    = warp >> 1;            // each warp handles 4 rows of one gate
    const int r0   = (warp & 1) * 4;       // first row within gate
    const float* Wbase = Ws[g] + (size_t)r0 * D_DIM;

    for (int tt = 0; tt < 16; ++tt) {
        const int t   = blockIdx.x * 16 + tt;
        const int idx = sentence[t];

        // stage embedding row into smem (256 x float4 = 1024 floats)
        const float4* src = (const float4*)(emb + (size_t)idx * E_DIM);
        ((float4*)xs)[tid] = src[tid];
        __syncthreads();

        float acc0 = 0.f, acc1 = 0.f, acc2 = 0.f, acc3 = 0.f;
        for (int k = lane; k < E_DIM; k += 32) {
            const float x = xs[k];
            acc0 = fmaf(x, Wbase[k],             acc0);
            acc1 = fmaf(x, Wbase[D_DIM + k],     acc1);
            acc2 = fmaf(x, Wbase[2 * D_DIM + k], acc2);
            acc3 = fmaf(x, Wbase[3 * D_DIM + k], acc3);
        }
        #pragma unroll
        for (int d = 16; d; d >>= 1) {
            acc0 += __shfl_down_sync(0xffffffffu, acc0, d);
            acc1 += __shfl_down_sync(0xffffffffu, acc1, d);
            acc2 += __shfl_down_sync(0xffffffffu, acc2, d);
            acc3 += __shfl_down_sync(0xffffffffu, acc3, d);
        }
        if (lane == 0) {
            float* dst = g_xproj + t * 32 + g * 8 + r0;
            const float* b = bs[g] + r0;
            dst[0] = acc0 + b[0];
            dst[1] = acc1 + b[1];
            dst[2] = acc2 + b[2];
            dst[3] = acc3 + b[3];
        }
        __syncthreads();
    }
}

// ---------------------------------------------------------------------------
// Phase 2: sequential LSTM scan. 1 block, 32 threads.
// lane = g*8 + w.  Quantum circuit per gate collapses to:
//   z_w = prod_{j<=w} cos(rx_j) * cos(angle_j)
// Lane (g,w) keeps its own c_w, h_w (replicated across the 4 gate groups).
// ---------------------------------------------------------------------------
__global__ __launch_bounds__(32)
void scan_kernel(const float* __restrict__ Wf, const float* __restrict__ Wi,
                 const float* __restrict__ Wu, const float* __restrict__ Wo,
                 const float* __restrict__ rxf, const float* __restrict__ rxi,
                 const float* __restrict__ rxu, const float* __restrict__ rxo)
{
    const int lane = threadIdx.x;
    const int g = lane >> 3;
    const int w = lane & 7;

    const float* Wg  = (g == 0) ? Wf  : (g == 1) ? Wi  : (g == 2) ? Wu  : Wo;
    const float* rxg = (g == 0) ? rxf : (g == 1) ? rxi : (g == 2) ? rxu : rxo;

    float Wh[8];
    #pragma unroll
    for (int j = 0; j < 8; ++j)
        Wh[j] = Wg[(size_t)w * D_DIM + E_DIM + j];

    const float crx = cosf(rxg[w]);
    // activation: gates f,i,o -> sigmoid(z); gate u -> tanh(z) = 2*sigmoid(2z)-1
    const float actScale = (g == 2) ? 2.f : 1.f;
    const float actMul   = (g == 2) ? 2.f : 1.f;
    const float actAdd   = (g == 2) ? -1.f : 0.f;

    float hw = 0.f, cw = 0.f;
    __shared__ float4 acts[2][8];   // [buffer][w] = (f, i, u, o)

    // prefetch pipeline (depth 4)
    float xp0 = g_xproj[0 * 32 + lane];
    float xp1 = g_xproj[1 * 32 + lane];
    float xp2 = g_xproj[2 * 32 + lane];
    float xp3 = g_xproj[3 * 32 + lane];

#define QLSTM_STEP(XP, TSTEP)                                                  \
    {                                                                          \
        float a = (XP);                                                        \
        _Pragma("unroll")                                                      \
        for (int j = 0; j < 8; ++j) {                                          \
            const float hj = __shfl_sync(0xffffffffu, hw, j, 8);               \
            a = fmaf(hj, Wh[j], a);                                            \
        }                                                                      \
        float z = crx * __cosf(a);                                             \
        float v;                                                               \
        v = __shfl_up_sync(0xffffffffu, z, 1, 8); if (w >= 1) z *= v;          \
        v = __shfl_up_sync(0xffffffffu, z, 2, 8); if (w >= 2) z *= v;          \
        v = __shfl_up_sync(0xffffffffu, z, 4, 8); if (w >= 4) z *= v;          \
        const float act = actMul / (1.f + __expf(-actScale * z)) + actAdd;     \
        ((float*)&acts[(TSTEP) & 1][w])[g] = act;                              \
        __syncwarp();                                                          \
        const float4 A = acts[(TSTEP) & 1][w];                                 \
        cw = fmaf(A.x, cw, A.y * A.z);                                         \
        const float e2 = __expf(-2.f * cw);                                    \
        hw = A.w * __fdividef(1.f - e2, 1.f + e2);                             \
        if (g == 0) g_outs[(TSTEP) * 8 + w] = hw;                              \
    }

    for (int t = 0; t < T_LEN; t += 4) {
        QLSTM_STEP(xp0, t);     xp0 = g_xproj[(t + 4) * 32 + lane];
        QLSTM_STEP(xp1, t + 1); xp1 = g_xproj[(t + 5) * 32 + lane];
        QLSTM_STEP(xp2, t + 2); xp2 = g_xproj[(t + 6) * 32 + lane];
        QLSTM_STEP(xp3, t + 3); xp3 = g_xproj[(t + 7) * 32 + lane];
    }
#undef QLSTM_STEP
}

// ---------------------------------------------------------------------------
// Phase 3: tag head.  out[t][w] = log( (prod_{j<=w} cos(logit_j) + 1)/2 + 1e-12 )
// One thread per timestep.
// ---------------------------------------------------------------------------
__global__ __launch_bounds__(256)
void tag_kernel(const float* __restrict__ Wtag, const float* __restrict__ btag,
                float* __restrict__ out)
{
    const int t = blockIdx.x * blockDim.x + threadIdx.x;
    if (t >= T_LEN) return;

    float h[8];
    #pragma unroll
    for (int j = 0; j < 8; ++j) h[j] = g_outs[t * 8 + j];

    float z = 1.f;
    float o[8];
    #pragma unroll
    for (int w = 0; w < 8; ++w) {
        float a = btag[w];
        #pragma unroll
        for (int j = 0; j < 8; ++j)
            a = fmaf(h[j], Wtag[w * 8 + j], a);
        z *= __cosf(a);
        o[w] = logf(fmaf(z, 0.5f, 0.5f) + 1e-12f);
    }
    float4* dst = (float4*)(out + t * 8);
    dst[0] = make_float4(o[0], o[1], o[2], o[3]);
    dst[1] = make_float4(o[4], o[5], o[6], o[7]);
}

// ---------------------------------------------------------------------------
extern "C" void kernel_launch(void* const* d_in, const int* in_sizes, int n_in,
                              void* d_out, int out_size)
{
    const int*   sentence = (const int*)  d_in[0];
    const float* emb      = (const float*)d_in[1];
    const float* Wf       = (const float*)d_in[2];
    const float* bf       = (const float*)d_in[3];
    const float* Wi       = (const float*)d_in[4];
    const float* bi       = (const float*)d_in[5];
    const float* Wu       = (const float*)d_in[6];
    const float* bu       = (const float*)d_in[7];
    const float* Wo       = (const float*)d_in[8];
    const float* bo       = (const float*)d_in[9];
    const float* rxf      = (const float*)d_in[10];
    const float* rxi      = (const float*)d_in[11];
    const float* rxu      = (const float*)d_in[12];
    const float* rxo      = (const float*)d_in[13];
    const float* Wtag     = (const float*)d_in[14];
    const float* btag     = (const float*)d_in[15];

    xproj_kernel<<<T_LEN / 16, 256>>>(sentence, emb, Wf, bf, Wi, bi, Wu, bu, Wo, bo);
    scan_kernel<<<1, 32>>>(Wf, Wi, Wu, Wo, rxf, rxi, rxu, rxo);
    tag_kernel<<<(T_LEN + 255) / 256, 256>>>(Wtag, btag, (float*)d_out);
}

// round 2
// speedup vs baseline: 1.3892x; 1.3892x over previous
#include <cuda_runtime.h>
#include <math.h>

#define T_LEN 2048
#define E_DIM 1024
#define D_DIM 1032   // E + H
#define FULLM 0xffffffffu

__device__ float g_xproj[(T_LEN + 8) * 32];  // [t][g*8+w], bias folded in
__device__ float g_outs[T_LEN * 8];          // h_t

__device__ __forceinline__ float tanhapx(float x) {
    float y;
    asm("tanh.approx.f32 %0, %1;" : "=f"(y) : "f"(x));
    return y;
}

// ---------------------------------------------------------------------------
// Phase 1: xproj[t][g][w] = emb[sentence[t]] . Wg[w] + bg[w]   (float4 version)
// 128 blocks x 256 threads, 16 timesteps per block.
// ---------------------------------------------------------------------------
__global__ __launch_bounds__(256)
void xproj_kernel(const int* __restrict__ sentence,
                  const float* __restrict__ emb,
                  const float* __restrict__ Wf, const float* __restrict__ bf,
                  const float* __restrict__ Wi, const float* __restrict__ bi,
                  const float* __restrict__ Wu, const float* __restrict__ bu,
                  const float* __restrict__ Wo, const float* __restrict__ bo)
{
    __shared__ float4 xs4[E_DIM / 4];
    const float* Ws[4] = {Wf, Wi, Wu, Wo};
    const float* bs[4] = {bf, bi, bu, bo};

    const int tid  = threadIdx.x;
    const int warp = tid >> 5;
    const int lane = tid & 31;
    const int g    = warp >> 1;
    const int r0   = (warp & 1) * 4;

    // Row base pointers (1032 floats/row = 4128 bytes, 16B-aligned)
    const float4* W0 = (const float4*)(Ws[g] + (size_t)(r0 + 0) * D_DIM);
    const float4* W1 = (const float4*)(Ws[g] + (size_t)(r0 + 1) * D_DIM);
    const float4* W2 = (const float4*)(Ws[g] + (size_t)(r0 + 2) * D_DIM);
    const float4* W3 = (const float4*)(Ws[g] + (size_t)(r0 + 3) * D_DIM);

    for (int tt = 0; tt < 16; ++tt) {
        const int t   = blockIdx.x * 16 + tt;
        const int idx = sentence[t];

        xs4[tid] = ((const float4*)(emb + (size_t)idx * E_DIM))[tid];
        __syncthreads();

        float a0 = 0.f, a1 = 0.f, a2 = 0.f, a3 = 0.f;
        #pragma unroll
        for (int j = 0; j < 8; ++j) {
            const int k4 = lane + 32 * j;
            const float4 x = xs4[k4];
            float4 w;
            w = __ldg(W0 + k4);
            a0 = fmaf(x.x, w.x, fmaf(x.y, w.y, fmaf(x.z, w.z, fmaf(x.w, w.w, a0))));
            w = __ldg(W1 + k4);
            a1 = fmaf(x.x, w.x, fmaf(x.y, w.y, fmaf(x.z, w.z, fmaf(x.w, w.w, a1))));
            w = __ldg(W2 + k4);
            a2 = fmaf(x.x, w.x, fmaf(x.y, w.y, fmaf(x.z, w.z, fmaf(x.w, w.w, a2))));
            w = __ldg(W3 + k4);
            a3 = fmaf(x.x, w.x, fmaf(x.y, w.y, fmaf(x.z, w.z, fmaf(x.w, w.w, a3))));
        }
        #pragma unroll
        for (int d = 16; d; d >>= 1) {
            a0 += __shfl_down_sync(FULLM, a0, d);
            a1 += __shfl_down_sync(FULLM, a1, d);
            a2 += __shfl_down_sync(FULLM, a2, d);
            a3 += __shfl_down_sync(FULLM, a3, d);
        }
        if (lane == 0) {
            float* dst = g_xproj + t * 32 + g * 8 + r0;
            const float* b = bs[g] + r0;
            dst[0] = a0 + b[0];
            dst[1] = a1 + b[1];
            dst[2] = a2 + b[2];
            dst[3] = a3 + b[3];
        }
        __syncthreads();
    }
}

// ---------------------------------------------------------------------------
// Phase 2: sequential LSTM scan. 1 block, 32 threads. lane = g*8 + w.
// z_w = [prod_{j<=w} cos(rx_j)] * [prod_{j<=w} cos(a_j)]
// All cross-lane traffic via shfl; activations via MUFU.TANH.
// ---------------------------------------------------------------------------
__global__ __launch_bounds__(32)
void scan_kernel(const float* __restrict__ Wf, const float* __restrict__ Wi,
                 const float* __restrict__ Wu, const float* __restrict__ Wo,
                 const float* __restrict__ rxf, const float* __restrict__ rxi,
                 const float* __restrict__ rxu, const float* __restrict__ rxo)
{
    const int lane = threadIdx.x;
    const int g = lane >> 3;
    const int w = lane & 7;

    const float* Wg  = (g == 0) ? Wf  : (g == 1) ? Wi  : (g == 2) ? Wu  : Wo;
    const float* rxg = (g == 0) ? rxf : (g == 1) ? rxi : (g == 2) ? rxu : rxo;

    float Wh[8];
    #pragma unroll
    for (int j = 0; j < 8; ++j)
        Wh[j] = Wg[(size_t)w * D_DIM + E_DIM + j];

    // Constant prefix product of cos(rx), folded with the sigmoid pre-scale.
    float K = 1.f;
    for (int j = 0; j <= w; ++j) K *= cosf(rxg[j]);
    // gates f,i,o: sigmoid(z) = 0.5*tanh(0.5*z)+0.5 ;  gate u: tanh(z)
    const float preMul  = (g == 2) ? 1.f : 0.5f;
    const float postMul = (g == 2) ? 1.f : 0.5f;
    const float postAdd = (g == 2) ? 0.f : 0.5f;
    K *= preMul;

    float hw = 0.f, cw = 0.f;

    // xp prefetch pipeline (depth 4)
    float xp0 = g_xproj[0 * 32 + lane];
    float xp1 = g_xproj[1 * 32 + lane];
    float xp2 = g_xproj[2 * 32 + lane];
    float xp3 = g_xproj[3 * 32 + lane];

#define QLSTM_STEP(XP, TSTEP)                                                   \
    {                                                                           \
        const float h0 = __shfl_sync(FULLM, hw, 0, 8);                          \
        const float h1 = __shfl_sync(FULLM, hw, 1, 8);                          \
        const float h2 = __shfl_sync(FULLM, hw, 2, 8);                          \
        const float h3 = __shfl_sync(FULLM, hw, 3, 8);                          \
        const float h4 = __shfl_sync(FULLM, hw, 4, 8);                          \
        const float h5 = __shfl_sync(FULLM, hw, 5, 8);                          \
        const float h6 = __shfl_sync(FULLM, hw, 6, 8);                          \
        const float h7 = __shfl_sync(FULLM, hw, 7, 8);                          \
        const float s0 = fmaf(h0, Wh[0], h1 * Wh[1]);                           \
        const float s1 = fmaf(h2, Wh[2], h3 * Wh[3]);                           \
        const float s2 = fmaf(h4, Wh[4], h5 * Wh[5]);                           \
        const float s3 = fmaf(h6, Wh[6], h7 * Wh[7]);                           \
        const float a  = ((XP) + (s0 + s1)) + (s2 + s3);                        \
        const float cz = __cosf(a);                                             \
        float m1 = __shfl_sync(FULLM, cz, (w - 1) & 7, 8);                      \
        float m2 = __shfl_sync(FULLM, cz, (w - 2) & 7, 8);                      \
        float m3 = __shfl_sync(FULLM, cz, (w - 3) & 7, 8);                      \
        float m4 = __shfl_sync(FULLM, cz, (w - 4) & 7, 8);                      \
        float m5 = __shfl_sync(FULLM, cz, (w - 5) & 7, 8);                      \
        float m6 = __shfl_sync(FULLM, cz, (w - 6) & 7, 8);                      \
        float m7 = __shfl_sync(FULLM, cz, (w - 7) & 7, 8);                      \
        m1 = (w >= 1) ? m1 : 1.f;                                               \
        m2 = (w >= 2) ? m2 : 1.f;                                               \
        m3 = (w >= 3) ? m3 : 1.f;                                               \
        m4 = (w >= 4) ? m4 : 1.f;                                               \
        m5 = (w >= 5) ? m5 : 1.f;                                               \
        m6 = (w >= 6) ? m6 : 1.f;                                               \
        m7 = (w >= 7) ? m7 : 1.f;                                               \
        const float pc  = ((cz * m1) * (m2 * m3)) * ((m4 * m5) * (m6 * m7));    \
        const float act = fmaf(tanhapx(pc * K), postMul, postAdd);              \
        const float f = __shfl_sync(FULLM, act, w,      32);                    \
        const float i = __shfl_sync(FULLM, act, 8 + w,  32);                    \
        const float u = __shfl_sync(FULLM, act, 16 + w, 32);                    \
        const float o = __shfl_sync(FULLM, act, 24 + w, 32);                    \
        cw = fmaf(f, cw, i * u);                                                \
        hw = o * tanhapx(cw);                                                   \
        if (g == 0) g_outs[(TSTEP) * 8 + w] = hw;                               \
    }

    for (int t = 0; t < T_LEN; t += 4) {
        QLSTM_STEP(xp0, t);     xp0 = g_xproj[(t + 4) * 32 + lane];
        QLSTM_STEP(xp1, t + 1); xp1 = g_xproj[(t + 5) * 32 + lane];
        QLSTM_STEP(xp2, t + 2); xp2 = g_xproj[(t + 6) * 32 + lane];
        QLSTM_STEP(xp3, t + 3); xp3 = g_xproj[(t + 7) * 32 + lane];
    }
#undef QLSTM_STEP
}

// ---------------------------------------------------------------------------
// Phase 3: tag head. out[t][w] = log( (prod_{j<=w} cos(logit_j) + 1)/2 + 1e-12 )
// ---------------------------------------------------------------------------
__global__ __launch_bounds__(256)
void tag_kernel(const float* __restrict__ Wtag, const float* __restrict__ btag,
                float* __restrict__ out)
{
    const int t = blockIdx.x * blockDim.x + threadIdx.x;
    if (t >= T_LEN) return;

    float h[8];
    #pragma unroll
    for (int j = 0; j < 8; ++j) h[j] = g_outs[t * 8 + j];

    float z = 1.f;
    float o[8];
    #pragma unroll
    for (int w = 0; w < 8; ++w) {
        float a = btag[w];
        #pragma unroll
        for (int j = 0; j < 8; ++j)
            a = fmaf(h[j], Wtag[w * 8 + j], a);
        z *= __cosf(a);
        o[w] = logf(fmaf(z, 0.5f, 0.5f) + 1e-12f);
    }
    float4* dst = (float4*)(out + t * 8);
    dst[0] = make_float4(o[0], o[1], o[2], o[3]);
    dst[1] = make_float4(o[4], o[5], o[6], o[7]);
}

// ---------------------------------------------------------------------------
extern "C" void kernel_launch(void* const* d_in, const int* in_sizes, int n_in,
                              void* d_out, int out_size)
{
    const int*   sentence = (const int*)  d_in[0];
    const float* emb      = (const float*)d_in[1];
    const float* Wf       = (const float*)d_in[2];
    const float* bf       = (const float*)d_in[3];
    const float* Wi       = (const float*)d_in[4];
    const float* bi       = (const float*)d_in[5];
    const float* Wu       = (const float*)d_in[6];
    const float* bu       = (const float*)d_in[7];
    const float* Wo       = (const float*)d_in[8];
    const float* bo       = (const float*)d_in[9];
    const float* rxf      = (const float*)d_in[10];
    const float* rxi      = (const float*)d_in[11];
    const float* rxu      = (const float*)d_in[12];
    const float* rxo      = (const float*)d_in[13];
    const float* Wtag     = (const float*)d_in[14];
    const float* btag     = (const float*)d_in[15];

    xproj_kernel<<<T_LEN / 16, 256>>>(sentence, emb, Wf, bf, Wi, bi, Wu, bu, Wo, bo);
    scan_kernel<<<1, 32>>>(Wf, Wi, Wu, Wo, rxf, rxi, rxu, rxo);
    tag_kernel<<<(T_LEN + 255) / 256, 256>>>(Wtag, btag, (float*)d_out);
}

// round 3
// speedup vs baseline: 11.5339x; 8.3027x over previous
#include <cuda_runtime.h>
#include <math.h>

#define T_LEN 2048
#define E_DIM 1024
#define D_DIM 1032   // E + H
#define FULLM 0xffffffffu

#define CHUNK 64     // emitted steps per scan block
#define WARM  64     // warmup steps (state contraction <=0.76/step -> 0.76^64 ~ 2e-8)
#define NCHUNK (T_LEN / CHUNK)

#define BLK_T 8      // timesteps per xproj block

__device__ float g_xproj[(T_LEN + 8) * 32];  // [t][g*8+w], bias folded in
__device__ float g_outs[T_LEN * 8];          // h_t

__device__ __forceinline__ float tanhapx(float x) {
    float y;
    asm("tanh.approx.f32 %0, %1;" : "=f"(y) : "f"(x));
    return y;
}

// ---------------------------------------------------------------------------
// Phase 1: xproj[t][g][w] = emb[sentence[t]] . Wg[w] + bg[w]
// 256 blocks x 256 threads, 8 timesteps per block, double-buffered smem.
// ---------------------------------------------------------------------------
__global__ __launch_bounds__(256)
void xproj_kernel(const int* __restrict__ sentence,
                  const float* __restrict__ emb,
                  const float* __restrict__ Wf, const float* __restrict__ bf,
                  const float* __restrict__ Wi, const float* __restrict__ bi,
                  const float* __restrict__ Wu, const float* __restrict__ bu,
                  const float* __restrict__ Wo, const float* __restrict__ bo)
{
    __shared__ float4 xs4[2][E_DIM / 4];
    const float* Ws[4] = {Wf, Wi, Wu, Wo};
    const float* bs[4] = {bf, bi, bu, bo};

    const int tid  = threadIdx.x;
    const int warp = tid >> 5;
    const int lane = tid & 31;
    const int g    = warp >> 1;
    const int r0   = (warp & 1) * 4;
    const int t0   = blockIdx.x * BLK_T;

    const float4* W0 = (const float4*)(Ws[g] + (size_t)(r0 + 0) * D_DIM);
    const float4* W1 = (const float4*)(Ws[g] + (size_t)(r0 + 1) * D_DIM);
    const float4* W2 = (const float4*)(Ws[g] + (size_t)(r0 + 2) * D_DIM);
    const float4* W3 = (const float4*)(Ws[g] + (size_t)(r0 + 3) * D_DIM);

    // prologue: stage row for tt=0
    xs4[0][tid] = ((const float4*)(emb + (size_t)sentence[t0] * E_DIM))[tid];

    #pragma unroll
    for (int tt = 0; tt < BLK_T; ++tt) {
        const int cur = tt & 1;
        // issue prefetch of next row before waiting
        float4 nxt;
        if (tt + 1 < BLK_T)
            nxt = ((const float4*)(emb + (size_t)sentence[t0 + tt + 1] * E_DIM))[tid];

        __syncthreads();   // xs4[cur] is now valid

        float a0 = 0.f, a1 = 0.f, a2 = 0.f, a3 = 0.f;
        #pragma unroll
        for (int j = 0; j < 8; ++j) {
            const int k4 = lane + 32 * j;
            const float4 x = xs4[cur][k4];
            float4 wv;
            wv = __ldg(W0 + k4);
            a0 = fmaf(x.x, wv.x, fmaf(x.y, wv.y, fmaf(x.z, wv.z, fmaf(x.w, wv.w, a0))));
            wv = __ldg(W1 + k4);
            a1 = fmaf(x.x, wv.x, fmaf(x.y, wv.y, fmaf(x.z, wv.z, fmaf(x.w, wv.w, a1))));
            wv = __ldg(W2 + k4);
            a2 = fmaf(x.x, wv.x, fmaf(x.y, wv.y, fmaf(x.z, wv.z, fmaf(x.w, wv.w, a2))));
            wv = __ldg(W3 + k4);
            a3 = fmaf(x.x, wv.x, fmaf(x.y, wv.y, fmaf(x.z, wv.z, fmaf(x.w, wv.w, a3))));
        }
        #pragma unroll
        for (int d = 16; d; d >>= 1) {
            a0 += __shfl_down_sync(FULLM, a0, d);
            a1 += __shfl_down_sync(FULLM, a1, d);
            a2 += __shfl_down_sync(FULLM, a2, d);
            a3 += __shfl_down_sync(FULLM, a3, d);
        }
        if (lane == 0) {
            float* dst = g_xproj + (t0 + tt) * 32 + g * 8 + r0;
            const float* b = bs[g] + r0;
            dst[0] = a0 + b[0];
            dst[1] = a1 + b[1];
            dst[2] = a2 + b[2];
            dst[3] = a3 + b[3];
        }
        // write next row into the other buffer (no one reads it until next sync)
        if (tt + 1 < BLK_T)
            xs4[1 - cur][tid] = nxt;
    }
}

// ---------------------------------------------------------------------------
// Phase 2: chunked LSTM scan. NCHUNK blocks x 32 threads; lane = g*8+w.
// Each block warms up WARM steps from zero state (forget gate <= 0.7311
// guarantees convergence), then emits CHUNK outputs.
// ---------------------------------------------------------------------------
__global__ __launch_bounds__(32)
void scan_kernel(const float* __restrict__ Wf, const float* __restrict__ Wi,
                 const float* __restrict__ Wu, const float* __restrict__ Wo,
                 const float* __restrict__ rxf, const float* __restrict__ rxi,
                 const float* __restrict__ rxu, const float* __restrict__ rxo)
{
    const int lane = threadIdx.x;
    const int g = lane >> 3;
    const int w = lane & 7;

    const float* Wg  = (g == 0) ? Wf  : (g == 1) ? Wi  : (g == 2) ? Wu  : Wo;
    const float* rxg = (g == 0) ? rxf : (g == 1) ? rxi : (g == 2) ? rxu : rxo;

    float Wh[8];
    #pragma unroll
    for (int j = 0; j < 8; ++j)
        Wh[j] = Wg[(size_t)w * D_DIM + E_DIM + j];

    float K = 1.f;
    for (int j = 0; j <= w; ++j) K *= cosf(rxg[j]);
    // f,i,o: sigmoid(z)=0.5*tanh(0.5z)+0.5 ; u: tanh(z)
    const float postMul = (g == 2) ? 1.f : 0.5f;
    const float postAdd = (g == 2) ? 0.f : 0.5f;
    K *= (g == 2) ? 1.f : 0.5f;

    const int tEmit  = blockIdx.x * CHUNK;
    const int tStart = (blockIdx.x == 0) ? 0 : (tEmit - WARM);
    const int tEnd   = tEmit + CHUNK;

    float hw = 0.f, cw = 0.f;

    float xp0 = g_xproj[(tStart + 0) * 32 + lane];
    float xp1 = g_xproj[(tStart + 1) * 32 + lane];
    float xp2 = g_xproj[(tStart + 2) * 32 + lane];
    float xp3 = g_xproj[(tStart + 3) * 32 + lane];

#define QLSTM_STEP(XP, TSTEP)                                                   \
    {                                                                           \
        const float h0 = __shfl_sync(FULLM, hw, 0, 8);                          \
        const float h1 = __shfl_sync(FULLM, hw, 1, 8);                          \
        const float h2 = __shfl_sync(FULLM, hw, 2, 8);                          \
        const float h3 = __shfl_sync(FULLM, hw, 3, 8);                          \
        const float h4 = __shfl_sync(FULLM, hw, 4, 8);                          \
        const float h5 = __shfl_sync(FULLM, hw, 5, 8);                          \
        const float h6 = __shfl_sync(FULLM, hw, 6, 8);                          \
        const float h7 = __shfl_sync(FULLM, hw, 7, 8);                          \
        const float s0 = fmaf(h0, Wh[0], h1 * Wh[1]);                           \
        const float s1 = fmaf(h2, Wh[2], h3 * Wh[3]);                           \
        const float s2 = fmaf(h4, Wh[4], h5 * Wh[5]);                           \
        const float s3 = fmaf(h6, Wh[6], h7 * Wh[7]);                           \
        const float a  = ((XP) + (s0 + s1)) + (s2 + s3);                        \
        const float cz = __cosf(a);                                             \
        float m1 = __shfl_sync(FULLM, cz, (w - 1) & 7, 8);                      \
        float m2 = __shfl_sync(FULLM, cz, (w - 2) & 7, 8);                      \
        float m3 = __shfl_sync(FULLM, cz, (w - 3) & 7, 8);                      \
        float m4 = __shfl_sync(FULLM, cz, (w - 4) & 7, 8);                      \
        float m5 = __shfl_sync(FULLM, cz, (w - 5) & 7, 8);                      \
        float m6 = __shfl_sync(FULLM, cz, (w - 6) & 7, 8);                      \
        float m7 = __shfl_sync(FULLM, cz, (w - 7) & 7, 8);                      \
        m1 = (w >= 1) ? m1 : 1.f;                                               \
        m2 = (w >= 2) ? m2 : 1.f;                                               \
        m3 = (w >= 3) ? m3 : 1.f;                                               \
        m4 = (w >= 4) ? m4 : 1.f;                                               \
        m5 = (w >= 5) ? m5 : 1.f;                                               \
        m6 = (w >= 6) ? m6 : 1.f;                                               \
        m7 = (w >= 7) ? m7 : 1.f;                                               \
        const float pc  = ((cz * m1) * (m2 * m3)) * ((m4 * m5) * (m6 * m7));    \
        const float act = fmaf(tanhapx(pc * K), postMul, postAdd);              \
        const float f = __shfl_sync(FULLM, act, w,      32);                    \
        const float i = __shfl_sync(FULLM, act, 8 + w,  32);                    \
        const float u = __shfl_sync(FULLM, act, 16 + w, 32);                    \
        const float o = __shfl_sync(FULLM, act, 24 + w, 32);                    \
        cw = fmaf(f, cw, i * u);                                                \
        hw = o * tanhapx(cw);                                                   \
        if (g == 0 && (TSTEP) >= tEmit) g_outs[(TSTEP) * 8 + w] = hw;           \
    }

    for (int t = tStart; t < tEnd; t += 4) {
        QLSTM_STEP(xp0, t);     xp0 = g_xproj[(t + 4) * 32 + lane];
        QLSTM_STEP(xp1, t + 1); xp1 = g_xproj[(t + 5) * 32 + lane];
        QLSTM_STEP(xp2, t + 2); xp2 = g_xproj[(t + 6) * 32 + lane];
        QLSTM_STEP(xp3, t + 3); xp3 = g_xproj[(t + 7) * 32 + lane];
    }
#undef QLSTM_STEP
}

// ---------------------------------------------------------------------------
// Phase 3: tag head. out[t][w] = log( (prod_{j<=w} cos(logit_j) + 1)/2 + 1e-12 )
// ---------------------------------------------------------------------------
__global__ __launch_bounds__(256)
void tag_kernel(const float* __restrict__ Wtag, const float* __restrict__ btag,
                float* __restrict__ out)
{
    const int t = blockIdx.x * blockDim.x + threadIdx.x;
    if (t >= T_LEN) return;

    float h[8];
    #pragma unroll
    for (int j = 0; j < 8; ++j) h[j] = g_outs[t * 8 + j];

    float z = 1.f;
    float o[8];
    #pragma unroll
    for (int w = 0; w < 8; ++w) {
        float a = btag[w];
        #pragma unroll
        for (int j = 0; j < 8; ++j)
            a = fmaf(h[j], Wtag[w * 8 + j], a);
        z *= __cosf(a);
        o[w] = logf(fmaf(z, 0.5f, 0.5f) + 1e-12f);
    }
    float4* dst = (float4*)(out + t * 8);
    dst[0] = make_float4(o[0], o[1], o[2], o[3]);
    dst[1] = make_float4(o[4], o[5], o[6], o[7]);
}

// ---------------------------------------------------------------------------
extern "C" void kernel_launch(void* const* d_in, const int* in_sizes, int n_in,
                              void* d_out, int out_size)
{
    const int*   sentence = (const int*)  d_in[0];
    const float* emb      = (const float*)d_in[1];
    const float* Wf       = (const float*)d_in[2];
    const float* bf       = (const float*)d_in[3];
    const float* Wi       = (const float*)d_in[4];
    const float* bi       = (const float*)d_in[5];
    const float* Wu       = (const float*)d_in[6];
    const float* bu       = (const float*)d_in[7];
    const float* Wo       = (const float*)d_in[8];
    const float* bo       = (const float*)d_in[9];
    const float* rxf      = (const float*)d_in[10];
    const float* rxi      = (const float*)d_in[11];
    const float* rxu      = (const float*)d_in[12];
    const float* rxo      = (const float*)d_in[13];
    const float* Wtag     = (const float*)d_in[14];
    const float* btag     = (const float*)d_in[15];

    xproj_kernel<<<T_LEN / BLK_T, 256>>>(sentence, emb, Wf, bf, Wi, bi, Wu, bu, Wo, bo);
    scan_kernel<<<NCHUNK, 32>>>(Wf, Wi, Wu, Wo, rxf, rxi, rxu, rxo);
    tag_kernel<<<(T_LEN + 255) / 256, 256>>>(Wtag, btag, (float*)d_out);
}

// round 4
// speedup vs baseline: 16.5981x; 1.4391x over previous
#include <cuda_runtime.h>
#include <math.h>

#define T_LEN 2048
#define E_DIM 1024
#define D_DIM 1032   // E + H
#define FULLM 0xffffffffu

#define CHUNK 16     // emitted steps per scan block
#define WARM  48     // warmup: f <= sigmoid(1)=0.7311 -> 0.7311^48 ~ 3e-7
#define NCHUNK (T_LEN / CHUNK)

#define NT 16        // timesteps per xproj block (128 blocks)

__device__ float g_xproj[(T_LEN + 8) * 32];  // [t][g*8+w], bias folded in
__device__ float g_outs[T_LEN * 8];          // h_t

__device__ __forceinline__ float tanhapx(float x) {
    float y;
    asm("tanh.approx.f32 %0, %1;" : "=f"(y) : "f"(x));
    return y;
}

// ---------------------------------------------------------------------------
// Phase 1: xproj[t][row] = emb[sentence[t]] . W[row] + b[row]
// 128 blocks x 1024 threads (32 warps). Each warp owns one (g,w) row of W,
// held entirely in registers (8 x float4 per lane). x streamed via smem,
// double-buffered. W is read from L2 exactly once per block.
// ---------------------------------------------------------------------------
__global__ __launch_bounds__(1024)
void xproj_kernel(const int* __restrict__ sentence,
                  const float* __restrict__ emb,
                  const float* __restrict__ Wf, const float* __restrict__ bf,
                  const float* __restrict__ Wi, const float* __restrict__ bi,
                  const float* __restrict__ Wu, const float* __restrict__ bu,
                  const float* __restrict__ Wo, const float* __restrict__ bo)
{
    __shared__ float4 xs4[2][E_DIM / 4];

    const int tid  = threadIdx.x;
    const int warp = tid >> 5;     // row = g*8 + w
    const int lane = tid & 31;
    const int g    = warp >> 3;
    const int w    = warp & 7;

    const float* Ws[4] = {Wf, Wi, Wu, Wo};
    const float* bs[4] = {bf, bi, bu, bo};

    // Load this warp's W row into registers (first 1024 of 1032 cols).
    // Row byte offset w*4128 is 16B-aligned.
    const float4* Wrow = (const float4*)(Ws[g] + (size_t)w * D_DIM);
    float4 Wr[8];
    #pragma unroll
    for (int k = 0; k < 8; ++k)
        Wr[k] = __ldg(Wrow + lane + 32 * k);
    const float bias = bs[g][w];

    const int t0 = blockIdx.x * NT;

    // prologue: stage x for tt=0
    if (tid < 256)
        xs4[0][tid] = ((const float4*)(emb + (size_t)sentence[t0] * E_DIM))[tid];

    #pragma unroll
    for (int tt = 0; tt < NT; ++tt) {
        const int cur = tt & 1;
        float4 nxt;
        if (tid < 256 && tt + 1 < NT)
            nxt = ((const float4*)(emb + (size_t)sentence[t0 + tt + 1] * E_DIM))[tid];

        __syncthreads();   // xs4[cur] valid

        float acc = 0.f;
        #pragma unroll
        for (int k = 0; k < 8; ++k) {
            const float4 x  = xs4[cur][lane + 32 * k];
            const float4 wv = Wr[k];
            acc = fmaf(x.x, wv.x, fmaf(x.y, wv.y, fmaf(x.z, wv.z, fmaf(x.w, wv.w, acc))));
        }
        #pragma unroll
        for (int d = 16; d; d >>= 1)
            acc += __shfl_down_sync(FULLM, acc, d);

        if (lane == 0)
            g_xproj[(t0 + tt) * 32 + warp] = acc + bias;

        if (tid < 256 && tt + 1 < NT)
            xs4[1 - cur][tid] = nxt;
    }
}

// ---------------------------------------------------------------------------
// Phase 2: chunked LSTM scan. NCHUNK blocks x 32 threads; lane = g*8+w.
// Each block warms up from zero state, then emits CHUNK outputs.
// ---------------------------------------------------------------------------
__global__ __launch_bounds__(32)
void scan_kernel(const float* __restrict__ Wf, const float* __restrict__ Wi,
                 const float* __restrict__ Wu, const float* __restrict__ Wo,
                 const float* __restrict__ rxf, const float* __restrict__ rxi,
                 const float* __restrict__ rxu, const float* __restrict__ rxo)
{
    const int lane = threadIdx.x;
    const int g = lane >> 3;
    const int w = lane & 7;

    const float* Wg  = (g == 0) ? Wf  : (g == 1) ? Wi  : (g == 2) ? Wu  : Wo;
    const float* rxg = (g == 0) ? rxf : (g == 1) ? rxi : (g == 2) ? rxu : rxo;

    float Wh[8];
    #pragma unroll
    for (int j = 0; j < 8; ++j)
        Wh[j] = Wg[(size_t)w * D_DIM + E_DIM + j];

    float K = 1.f;
    for (int j = 0; j <= w; ++j) K *= cosf(rxg[j]);
    // f,i,o: sigmoid(z)=0.5*tanh(0.5z)+0.5 ; u: tanh(z)
    const float postMul = (g == 2) ? 1.f : 0.5f;
    const float postAdd = (g == 2) ? 0.f : 0.5f;
    K *= (g == 2) ? 1.f : 0.5f;

    const int tEmit  = blockIdx.x * CHUNK;
    const int tStart = (tEmit > WARM) ? (tEmit - WARM) : 0;
    const int tEnd   = tEmit + CHUNK;

    float hw = 0.f, cw = 0.f;

    float xp0 = g_xproj[(tStart + 0) * 32 + lane];
    float xp1 = g_xproj[(tStart + 1) * 32 + lane];
    float xp2 = g_xproj[(tStart + 2) * 32 + lane];
    float xp3 = g_xproj[(tStart + 3) * 32 + lane];

#define QLSTM_STEP(XP, TSTEP)                                                   \
    {                                                                           \
        const float h0 = __shfl_sync(FULLM, hw, 0, 8);                          \
        const float h1 = __shfl_sync(FULLM, hw, 1, 8);                          \
        const float h2 = __shfl_sync(FULLM, hw, 2, 8);                          \
        const float h3 = __shfl_sync(FULLM, hw, 3, 8);                          \
        const float h4 = __shfl_sync(FULLM, hw, 4, 8);                          \
        const float h5 = __shfl_sync(FULLM, hw, 5, 8);                          \
        const float h6 = __shfl_sync(FULLM, hw, 6, 8);                          \
        const float h7 = __shfl_sync(FULLM, hw, 7, 8);                          \
        const float s0 = fmaf(h0, Wh[0], h1 * Wh[1]);                           \
        const float s1 = fmaf(h2, Wh[2], h3 * Wh[3]);                           \
        const float s2 = fmaf(h4, Wh[4], h5 * Wh[5]);                           \
        const float s3 = fmaf(h6, Wh[6], h7 * Wh[7]);                           \
        const float a  = ((XP) + (s0 + s1)) + (s2 + s3);                        \
        const float cz = __cosf(a);                                             \
        float m1 = __shfl_sync(FULLM, cz, (w - 1) & 7, 8);                      \
        float m2 = __shfl_sync(FULLM, cz, (w - 2) & 7, 8);                      \
        float m3 = __shfl_sync(FULLM, cz, (w - 3) & 7, 8);                      \
        float m4 = __shfl_sync(FULLM, cz, (w - 4) & 7, 8);                      \
        float m5 = __shfl_sync(FULLM, cz, (w - 5) & 7, 8);                      \
        float m6 = __shfl_sync(FULLM, cz, (w - 6) & 7, 8);                      \
        float m7 = __shfl_sync(FULLM, cz, (w - 7) & 7, 8);                      \
        m1 = (w >= 1) ? m1 : 1.f;                                               \
        m2 = (w >= 2) ? m2 : 1.f;                                               \
        m3 = (w >= 3) ? m3 : 1.f;                                               \
        m4 = (w >= 4) ? m4 : 1.f;                                               \
        m5 = (w >= 5) ? m5 : 1.f;                                               \
        m6 = (w >= 6) ? m6 : 1.f;                                               \
        m7 = (w >= 7) ? m7 : 1.f;                                               \
        const float pc  = ((cz * m1) * (m2 * m3)) * ((m4 * m5) * (m6 * m7));    \
        const float act = fmaf(tanhapx(pc * K), postMul, postAdd);              \
        const float f = __shfl_sync(FULLM, act, w,      32);                    \
        const float i = __shfl_sync(FULLM, act, 8 + w,  32);                    \
        const float u = __shfl_sync(FULLM, act, 16 + w, 32);                    \
        const float o = __shfl_sync(FULLM, act, 24 + w, 32);                    \
        cw = fmaf(f, cw, i * u);                                                \
        hw = o * tanhapx(cw);                                                   \
        if (g == 0 && (TSTEP) >= tEmit) g_outs[(TSTEP) * 8 + w] = hw;           \
    }

    for (int t = tStart; t < tEnd; t += 4) {
        QLSTM_STEP(xp0, t);     xp0 = g_xproj[(t + 4) * 32 + lane];
        QLSTM_STEP(xp1, t + 1); xp1 = g_xproj[(t + 5) * 32 + lane];
        QLSTM_STEP(xp2, t + 2); xp2 = g_xproj[(t + 6) * 32 + lane];
        QLSTM_STEP(xp3, t + 3); xp3 = g_xproj[(t + 7) * 32 + lane];
    }
#undef QLSTM_STEP
}

// ---------------------------------------------------------------------------
// Phase 3: tag head. out[t][w] = log( (prod_{j<=w} cos(logit_j) + 1)/2 + 1e-12 )
// ---------------------------------------------------------------------------
__global__ __launch_bounds__(256)
void tag_kernel(const float* __restrict__ Wtag, const float* __restrict__ btag,
                float* __restrict__ out)
{
    const int t = blockIdx.x * blockDim.x + threadIdx.x;
    if (t >= T_LEN) return;

    const float4 h01 = ((const float4*)(g_outs + t * 8))[0];
    const float4 h23 = ((const float4*)(g_outs + t * 8))[1];
    const float h[8] = {h01.x, h01.y, h01.z, h01.w, h23.x, h23.y, h23.z, h23.w};

    float z = 1.f;
    float o[8];
    #pragma unroll
    for (int w = 0; w < 8; ++w) {
        float a = btag[w];
        #pragma unroll
        for (int j = 0; j < 8; ++j)
            a = fmaf(h[j], Wtag[w * 8 + j], a);
        z *= __cosf(a);
        o[w] = __logf(fmaf(z, 0.5f, 0.5f) + 1e-12f);
    }
    float4* dst = (float4*)(out + t * 8);
    dst[0] = make_float4(o[0], o[1], o[2], o[3]);
    dst[1] = make_float4(o[4], o[5], o[6], o[7]);
}

// ---------------------------------------------------------------------------
extern "C" void kernel_launch(void* const* d_in, const int* in_sizes, int n_in,
                              void* d_out, int out_size)
{
    const int*   sentence = (const int*)  d_in[0];
    const float* emb      = (const float*)d_in[1];
    const float* Wf       = (const float*)d_in[2];
    const float* bf       = (const float*)d_in[3];
    const float* Wi       = (const float*)d_in[4];
    const float* bi       = (const float*)d_in[5];
    const float* Wu       = (const float*)d_in[6];
    const float* bu       = (const float*)d_in[7];
    const float* Wo       = (const float*)d_in[8];
    const float* bo       = (const float*)d_in[9];
    const float* rxf      = (const float*)d_in[10];
    const float* rxi      = (const float*)d_in[11];
    const float* rxu      = (const float*)d_in[12];
    const float* rxo      = (const float*)d_in[13];
    const float* Wtag     = (const float*)d_in[14];
    const float* btag     = (const float*)d_in[15];

    xproj_kernel<<<T_LEN / NT, 1024>>>(sentence, emb, Wf, bf, Wi, bi, Wu, bu, Wo, bo);
    scan_kernel<<<NCHUNK, 32>>>(Wf, Wi, Wu, Wo, rxf, rxi, rxu, rxo);
    tag_kernel<<<(T_LEN + 255) / 256, 256>>>(Wtag, btag, (float*)d_out);
}

// round 5
// speedup vs baseline: 22.9713x; 1.3840x over previous
#include <cuda_runtime.h>
#include <math.h>

#define T_LEN 2048
#define E_DIM 1024
#define D_DIM 1032   // E + H
#define FULLM 0xffffffffu

#define CHUNK 8      // emitted steps per scan block
#define WARM  40     // warmup steps from zero state
#define NCHUNK (T_LEN / CHUNK)

#define NT 16        // timesteps per xproj block (128 blocks)

__device__ float g_xproj[(T_LEN + 8) * 32];  // [t][g*8+w], bias folded in

__device__ __forceinline__ float tanhapx(float x) {
    float y;
    asm("tanh.approx.f32 %0, %1;" : "=f"(y) : "f"(x));
    return y;
}

// ---------------------------------------------------------------------------
// Phase 1: xproj[t][g*8+w] = emb[sentence[t]] . Wg[w] + bg[w]
// 128 blocks x 256 threads (8 warps). Warp w holds ALL FOUR gates' row w of W
// in registers (4 x 8 float4 = 128 regs/lane). x is read straight from gmem
// (L1 broadcast across the 8 warps) -- no smem, no block syncs.
// ---------------------------------------------------------------------------
__global__ __launch_bounds__(256, 1)
void xproj_kernel(const int* __restrict__ sentence,
                  const float* __restrict__ emb,
                  const float* __restrict__ Wf, const float* __restrict__ bf,
                  const float* __restrict__ Wi, const float* __restrict__ bi,
                  const float* __restrict__ Wu, const float* __restrict__ bu,
                  const float* __restrict__ Wo, const float* __restrict__ bo)
{
    const int warp = threadIdx.x >> 5;   // wire w (0..7)
    const int lane = threadIdx.x & 31;
    const int w    = warp;

    // Per-gate W row w -> registers.
    const float4* Wp0 = (const float4*)(Wf + (size_t)w * D_DIM);
    const float4* Wp1 = (const float4*)(Wi + (size_t)w * D_DIM);
    const float4* Wp2 = (const float4*)(Wu + (size_t)w * D_DIM);
    const float4* Wp3 = (const float4*)(Wo + (size_t)w * D_DIM);

    float4 W0[8], W1[8], W2[8], W3[8];
    #pragma unroll
    for (int k = 0; k < 8; ++k) {
        W0[k] = __ldg(Wp0 + lane + 32 * k);
        W1[k] = __ldg(Wp1 + lane + 32 * k);
        W2[k] = __ldg(Wp2 + lane + 32 * k);
        W3[k] = __ldg(Wp3 + lane + 32 * k);
    }
    const float b0 = bf[w], b1 = bi[w], b2 = bu[w], b3 = bo[w];

    const int t0 = blockIdx.x * NT;

    #pragma unroll 2
    for (int tt = 0; tt < NT; ++tt) {
        const int t   = t0 + tt;
        const int idx = __ldg(sentence + t);
        const float4* xp = (const float4*)(emb + (size_t)idx * E_DIM);

        float a0 = 0.f, a1 = 0.f, a2 = 0.f, a3 = 0.f;
        #pragma unroll
        for (int k = 0; k < 8; ++k) {
            const float4 x = __ldg(xp + lane + 32 * k);
            a0 = fmaf(x.x, W0[k].x, fmaf(x.y, W0[k].y, fmaf(x.z, W0[k].z, fmaf(x.w, W0[k].w, a0))));
            a1 = fmaf(x.x, W1[k].x, fmaf(x.y, W1[k].y, fmaf(x.z, W1[k].z, fmaf(x.w, W1[k].w, a1))));
            a2 = fmaf(x.x, W2[k].x, fmaf(x.y, W2[k].y, fmaf(x.z, W2[k].z, fmaf(x.w, W2[k].w, a2))));
            a3 = fmaf(x.x, W3[k].x, fmaf(x.y, W3[k].y, fmaf(x.z, W3[k].z, fmaf(x.w, W3[k].w, a3))));
        }
        #pragma unroll
        for (int d = 16; d; d >>= 1) {
            a0 += __shfl_down_sync(FULLM, a0, d);
            a1 += __shfl_down_sync(FULLM, a1, d);
            a2 += __shfl_down_sync(FULLM, a2, d);
            a3 += __shfl_down_sync(FULLM, a3, d);
        }
        if (lane == 0) {
            float* dst = g_xproj + t * 32 + w;
            dst[0]  = a0 + b0;
            dst[8]  = a1 + b1;
            dst[16] = a2 + b2;
            dst[24] = a3 + b3;
        }
    }
}

// ---------------------------------------------------------------------------
// Phase 2+3: chunked LSTM scan with fused tag head.
// NCHUNK blocks x 32 threads; lane = g*8+w. Warm up WARM steps from zero
// state, emit CHUNK h vectors into smem, then lanes 0..CHUNK-1 each compute
// the 8 tag outputs for one timestep and write the final result.
// ---------------------------------------------------------------------------
__global__ __launch_bounds__(32)
void scan_kernel(const float* __restrict__ Wf, const float* __restrict__ Wi,
                 const float* __restrict__ Wu, const float* __restrict__ Wo,
                 const float* __restrict__ rxf, const float* __restrict__ rxi,
                 const float* __restrict__ rxu, const float* __restrict__ rxo,
                 const float* __restrict__ Wtag, const float* __restrict__ btag,
                 float* __restrict__ out)
{
    const int lane = threadIdx.x;
    const int g = lane >> 3;
    const int w = lane & 7;

    const float* Wg  = (g == 0) ? Wf  : (g == 1) ? Wi  : (g == 2) ? Wu  : Wo;
    const float* rxg = (g == 0) ? rxf : (g == 1) ? rxi : (g == 2) ? rxu : rxo;

    float Wh[8];
    #pragma unroll
    for (int j = 0; j < 8; ++j)
        Wh[j] = Wg[(size_t)w * D_DIM + E_DIM + j];

    float K = 1.f;
    for (int j = 0; j <= w; ++j) K *= cosf(rxg[j]);
    // f,i,o: sigmoid(z)=0.5*tanh(0.5z)+0.5 ; u: tanh(z)
    const float postMul = (g == 2) ? 1.f : 0.5f;
    const float postAdd = (g == 2) ? 0.f : 0.5f;
    K *= (g == 2) ? 1.f : 0.5f;

    const int tEmit  = blockIdx.x * CHUNK;
    const int tStart = (tEmit > WARM) ? (tEmit - WARM) : 0;
    const int tEnd   = tEmit + CHUNK;

    __shared__ float sh_h[CHUNK][8];

    float hw = 0.f, cw = 0.f;

    float xp0 = g_xproj[(tStart + 0) * 32 + lane];
    float xp1 = g_xproj[(tStart + 1) * 32 + lane];
    float xp2 = g_xproj[(tStart + 2) * 32 + lane];
    float xp3 = g_xproj[(tStart + 3) * 32 + lane];

#define QLSTM_STEP(XP, TSTEP)                                                   \
    {                                                                           \
        const float h0 = __shfl_sync(FULLM, hw, 0, 8);                          \
        const float h1 = __shfl_sync(FULLM, hw, 1, 8);                          \
        const float h2 = __shfl_sync(FULLM, hw, 2, 8);                          \
        const float h3 = __shfl_sync(FULLM, hw, 3, 8);                          \
        const float h4 = __shfl_sync(FULLM, hw, 4, 8);                          \
        const float h5 = __shfl_sync(FULLM, hw, 5, 8);                          \
        const float h6 = __shfl_sync(FULLM, hw, 6, 8);                          \
        const float h7 = __shfl_sync(FULLM, hw, 7, 8);                          \
        const float s0 = fmaf(h0, Wh[0], h1 * Wh[1]);                           \
        const float s1 = fmaf(h2, Wh[2], h3 * Wh[3]);                           \
        const float s2 = fmaf(h4, Wh[4], h5 * Wh[5]);                           \
        const float s3 = fmaf(h6, Wh[6], h7 * Wh[7]);                           \
        const float a  = ((XP) + (s0 + s1)) + (s2 + s3);                        \
        const float cz = __cosf(a);                                             \
        float m1 = __shfl_sync(FULLM, cz, (w - 1) & 7, 8);                      \
        float m2 = __shfl_sync(FULLM, cz, (w - 2) & 7, 8);                      \
        float m3 = __shfl_sync(FULLM, cz, (w - 3) & 7, 8);                      \
        float m4 = __shfl_sync(FULLM, cz, (w - 4) & 7, 8);                      \
        float m5 = __shfl_sync(FULLM, cz, (w - 5) & 7, 8);                      \
        float m6 = __shfl_sync(FULLM, cz, (w - 6) & 7, 8);                      \
        float m7 = __shfl_sync(FULLM, cz, (w - 7) & 7, 8);                      \
        m1 = (w >= 1) ? m1 : 1.f;                                               \
        m2 = (w >= 2) ? m2 : 1.f;                                               \
        m3 = (w >= 3) ? m3 : 1.f;                                               \
        m4 = (w >= 4) ? m4 : 1.f;                                               \
        m5 = (w >= 5) ? m5 : 1.f;                                               \
        m6 = (w >= 6) ? m6 : 1.f;                                               \
        m7 = (w >= 7) ? m7 : 1.f;                                               \
        const float pc  = ((cz * m1) * (m2 * m3)) * ((m4 * m5) * (m6 * m7));    \
        const float act = fmaf(tanhapx(pc * K), postMul, postAdd);              \
        const float f = __shfl_sync(FULLM, act, w,      32);                    \
        const float i = __shfl_sync(FULLM, act, 8 + w,  32);                    \
        const float u = __shfl_sync(FULLM, act, 16 + w, 32);                    \
        const float o = __shfl_sync(FULLM, act, 24 + w, 32);                    \
        cw = fmaf(f, cw, i * u);                                                \
        hw = o * tanhapx(cw);                                                   \
        if (g == 0 && (TSTEP) >= tEmit) sh_h[(TSTEP) - tEmit][w] = hw;          \
    }

    for (int t = tStart; t < tEnd; t += 4) {
        QLSTM_STEP(xp0, t);     xp0 = g_xproj[(t + 4) * 32 + lane];
        QLSTM_STEP(xp1, t + 1); xp1 = g_xproj[(t + 5) * 32 + lane];
        QLSTM_STEP(xp2, t + 2); xp2 = g_xproj[(t + 6) * 32 + lane];
        QLSTM_STEP(xp3, t + 3); xp3 = g_xproj[(t + 7) * 32 + lane];
    }
#undef QLSTM_STEP

    __syncwarp();

    // Fused tag head: lane tl handles timestep tEmit + tl.
    if (lane < CHUNK) {
        float h[8];
        #pragma unroll
        for (int j = 0; j < 8; ++j) h[j] = sh_h[lane][j];

        float z = 1.f;
        float o[8];
        #pragma unroll
        for (int ww = 0; ww < 8; ++ww) {
            float a = __ldg(btag + ww);
            #pragma unroll
            for (int j = 0; j < 8; ++j)
                a = fmaf(h[j], __ldg(Wtag + ww * 8 + j), a);
            z *= __cosf(a);
            o[ww] = __logf(fmaf(z, 0.5f, 0.5f) + 1e-12f);
        }
        float4* dst = (float4*)(out + (tEmit + lane) * 8);
        dst[0] = make_float4(o[0], o[1], o[2], o[3]);
        dst[1] = make_float4(o[4], o[5], o[6], o[7]);
    }
}

// ---------------------------------------------------------------------------
extern "C" void kernel_launch(void* const* d_in, const int* in_sizes, int n_in,
                              void* d_out, int out_size)
{
    const int*   sentence = (const int*)  d_in[0];
    const float* emb      = (const float*)d_in[1];
    const float* Wf       = (const float*)d_in[2];
    const float* bf       = (const float*)d_in[3];
    const float* Wi       = (const float*)d_in[4];
    const float* bi       = (const float*)d_in[5];
    const float* Wu       = (const float*)d_in[6];
    const float* bu       = (const float*)d_in[7];
    const float* Wo       = (const float*)d_in[8];
    const float* bo       = (const float*)d_in[9];
    const float* rxf      = (const float*)d_in[10];
    const float* rxi      = (const float*)d_in[11];
    const float* rxu      = (const float*)d_in[12];
    const float* rxo      = (const float*)d_in[13];
    const float* Wtag     = (const float*)d_in[14];
    const float* btag     = (const float*)d_in[15];

    xproj_kernel<<<T_LEN / NT, 256>>>(sentence, emb, Wf, bf, Wi, bi, Wu, bu, Wo, bo);
    scan_kernel<<<NCHUNK, 32>>>(Wf, Wi, Wu, Wo, rxf, rxi, rxu, rxo,
                                Wtag, btag, (float*)d_out);
}